// round 5
// baseline (speedup 1.0000x reference)
#include <cuda_runtime.h>
#include <math.h>

// Problem dims
#define BB   64
#define TT   512
#define DIN  64
#define DM   512
#define DOUT 64

// Launch shape: 128 CTAs (4 row-blocks x 32 col-blocks), 128 threads.
#define NCTA 128
#define NTHR 128
#define RB   16   // batch rows per CTA
#define CB   16   // h columns per CTA
#define APAD 4    // activation smem row pad (floats)
#define WPAD 2    // weight smem row pad (float2)

// Ping-pong hidden state in global (L2-resident: 2*2*128KB = 512KB)
__device__ float g_h0[2][BB * DM];
__device__ float g_h1[2][BB * DM];
// Epoch-parity barrier flags (stateless across graph replays: compared by == epoch,
// and every slot is rewritten every other epoch, so stale values can never match).
__device__ volatile unsigned g_flags[2][NCTA];

struct __align__(16) Smem {
    float  sA[RB][DM + APAD];        // K=512 activation operand (h0 side)
    float  sB[RB][DM + APAD];        // K=512 activation operand (h1_old side)
    float  sX[RB][DIN + APAD];       // x_t tile
    float2 whh0T[8][DM + WPAD];      // [colpair][k] slices of Whh0
    float2 wih1T[8][DM + WPAD];
    float2 whh1T[8][DM + WPAD];
    float2 wih0T[8][DIN + WPAD];
    float2 woutT[DM];                // this CTA's 2 output columns of Wout
    float2 red[RB][8];               // out-GEMM k-split reduction
    float  cbias0[CB];
    float  cbias1[CB];
    float  cbout[2];
};

// ---- packed f32x2 helpers (Blackwell FFMA2: 2x fp32 FMA throughput) ----
__device__ __forceinline__ unsigned long long pack2(float lo, float hi) {
    unsigned long long r;
    asm("mov.b64 %0, {%1, %2};" : "=l"(r) : "f"(lo), "f"(hi));
    return r;
}
__device__ __forceinline__ void unpack2(unsigned long long v, float &lo, float &hi) {
    asm("mov.b64 {%0, %1}, %2;" : "=f"(lo), "=f"(hi) : "l"(v));
}
__device__ __forceinline__ void fma2(unsigned long long &d, unsigned long long a,
                                     unsigned long long b) {
    asm("fma.rn.f32x2 %0, %1, %2, %0;" : "+l"(d) : "l"(a), "l"(b));
}

// C[r][c0..c0+1] += sum_k a_row[k] * wcol[k]   (wcol[k] = packed pair of 2 cols)
// Two accumulators break the FFMA dependency chain (lat 4 vs rt 2).
__device__ __forceinline__ void gemm_rc(const float *__restrict__ a_row,
                                        const float2 *__restrict__ wcol, int K,
                                        unsigned long long &acc0,
                                        unsigned long long &acc1) {
    const float4 *av = (const float4 *)a_row;
    const float4 *wv = (const float4 *)wcol;
    const int n8 = K >> 3;
#pragma unroll 2
    for (int k8 = 0; k8 < n8; k8++) {
        float4 a0 = av[2 * k8 + 0];
        float4 a1 = av[2 * k8 + 1];
        float4 w0 = wv[4 * k8 + 0];
        float4 w1 = wv[4 * k8 + 1];
        float4 w2 = wv[4 * k8 + 2];
        float4 w3 = wv[4 * k8 + 3];
        fma2(acc0, pack2(a0.x, a0.x), pack2(w0.x, w0.y));
        fma2(acc1, pack2(a0.y, a0.y), pack2(w0.z, w0.w));
        fma2(acc0, pack2(a0.z, a0.z), pack2(w1.x, w1.y));
        fma2(acc1, pack2(a0.w, a0.w), pack2(w1.z, w1.w));
        fma2(acc0, pack2(a1.x, a1.x), pack2(w2.x, w2.y));
        fma2(acc1, pack2(a1.y, a1.y), pack2(w2.z, w2.w));
        fma2(acc0, pack2(a1.z, a1.z), pack2(w3.x, w3.y));
        fma2(acc1, pack2(a1.w, a1.w), pack2(w3.z, w3.w));
    }
}

// Distributed-poll grid barrier. Each of the 128 threads polls one CTA's flag;
// epoch-parity double buffering makes overwrite-before-observe impossible
// (a CTA can only be one barrier ahead of any unarrived peer).
__device__ __forceinline__ void grid_barrier(unsigned e) {
    __threadfence();
    __syncthreads();
    if (threadIdx.x == 0) g_flags[e & 1u][blockIdx.x] = e;
    while (!__syncthreads_and(g_flags[e & 1u][threadIdx.x] == e)) {
    }
    __threadfence();
}

// out_{tt} = h1_rows(sB) @ Wout_slice + bout  (k-split 8-way + smem reduce)
__device__ __forceinline__ void out_step(Smem &S, float *__restrict__ out, int r0,
                                         int oc0, int r, int cp, int tid, int tt) {
    unsigned long long acc0 = pack2(0.f, 0.f), acc1 = pack2(0.f, 0.f);
    gemm_rc(&S.sB[r][cp * 64], &S.woutT[cp * 64], 64, acc0, acc1);
    float a, b, c, d;
    unpack2(acc0, a, b);
    unpack2(acc1, c, d);
    S.red[r][cp] = make_float2(a + c, b + d);
    __syncthreads();
    if (tid < RB) {
        float s0 = S.cbout[0], s1 = S.cbout[1];
#pragma unroll
        for (int j = 0; j < 8; j++) {
            float2 p = S.red[tid][j];
            s0 += p.x;
            s1 += p.y;
        }
        *(float2 *)&out[((size_t)(r0 + tid) * TT + tt) * DOUT + oc0] =
            make_float2(s0, s1);
    }
}

__global__ void __launch_bounds__(NTHR, 1)
rnn_persistent_kernel(const float *__restrict__ data, const float *__restrict__ Wih0,
                      const float *__restrict__ bih0, const float *__restrict__ Whh0,
                      const float *__restrict__ bhh0, const float *__restrict__ Wih1,
                      const float *__restrict__ bih1, const float *__restrict__ Whh1,
                      const float *__restrict__ bhh1, const float *__restrict__ Wout,
                      const float *__restrict__ bout, float *__restrict__ out) {
    extern __shared__ char smem_raw[];
    Smem &S = *reinterpret_cast<Smem *>(smem_raw);

    const int tid = threadIdx.x;
    const int cta = blockIdx.x;
    const int rb = cta >> 5;        // 0..3
    const int cb = cta & 31;        // 0..31
    const int r0 = rb * RB;         // batch-row base
    const int c0 = cb * CB;         // h-col base
    const int oc0 = cb * 2;         // out-col base (2 cols per CTA)
    const int r = tid & 15;         // this thread's row in tile
    const int cp = tid >> 4;        // this thread's colpair (0..7)

    // ---- one-time: weights -> smem (col-pair transposed) ----
    for (int idx = tid; idx < 8 * DM; idx += NTHR) {
        int icp = idx >> 9, k = idx & (DM - 1);
        int c = c0 + icp * 2;
        S.whh0T[icp][k] = *(const float2 *)&Whh0[k * DM + c];
        S.wih1T[icp][k] = *(const float2 *)&Wih1[k * DM + c];
        S.whh1T[icp][k] = *(const float2 *)&Whh1[k * DM + c];
    }
    for (int idx = tid; idx < 8 * DIN; idx += NTHR) {
        int icp = idx >> 6, k = idx & (DIN - 1);
        S.wih0T[icp][k] = *(const float2 *)&Wih0[k * DM + c0 + icp * 2];
    }
    for (int k = tid; k < DM; k += NTHR)
        S.woutT[k] = *(const float2 *)&Wout[k * DOUT + oc0];
    if (tid < CB) {
        S.cbias0[tid] = bih0[c0 + tid] + bhh0[c0 + tid];
        S.cbias1[tid] = bih1[c0 + tid] + bhh1[c0 + tid];
    }
    if (tid < 2) S.cbout[tid] = bout[oc0 + tid];
    __syncthreads();

    unsigned epoch = 0;

#pragma unroll 1
    for (int t = 0; t < TT; t++) {
        const int nb = t & 1;   // buffer written this step
        const int ob = nb ^ 1;  // buffer from previous step

        // ---- Phase A staging: sX = x_t rows; sB = h1_old rows (t>0).
        // sA already holds h0_old rows (staged during previous phase B).
        for (int idx = tid; idx < RB * (DIN / 4); idx += NTHR) {
            int i = idx >> 4, j = idx & 15;
            float4 v = *(const float4 *)&data[((size_t)(r0 + i) * TT + t) * DIN + j * 4];
            *(float4 *)&S.sX[i][j * 4] = v;
        }
        if (t > 0) {
#pragma unroll 4
            for (int it = 0; it < RB; it++) {
                float4 v = *(const float4 *)&g_h1[ob][(r0 + it) * DM + tid * 4];
                *(float4 *)&S.sB[it][tid * 4] = v;
            }
        }
        __syncthreads();

        // ---- Phase A compute: h0_new = tanh(x@Wih0 + h0_old@Whh0 + bias) ----
        {
            unsigned long long acc0 = pack2(S.cbias0[cp * 2], S.cbias0[cp * 2 + 1]);
            unsigned long long acc1 = pack2(0.f, 0.f);
            gemm_rc(&S.sX[r][0], &S.wih0T[cp][0], DIN, acc0, acc1);
            if (t > 0) gemm_rc(&S.sA[r][0], &S.whh0T[cp][0], DM, acc0, acc1);
            float a, b, c, d;
            unpack2(acc0, a, b);
            unpack2(acc1, c, d);
            float v0 = tanhf(a + c), v1 = tanhf(b + d);
            *(float2 *)&g_h0[nb][(r0 + r) * DM + c0 + cp * 2] = make_float2(v0, v1);
        }
        // out_{t-1} = h1_old @ Wout + bout  (h1_old rows are in sB)
        if (t > 0) out_step(S, out, r0, oc0, r, cp, tid, t - 1);

        grid_barrier(++epoch);  // h0_new globally complete

        // ---- Phase B staging: sA = h0_new rows (also h0_old for next step) ----
#pragma unroll 4
        for (int it = 0; it < RB; it++) {
            float4 v = *(const float4 *)&g_h0[nb][(r0 + it) * DM + tid * 4];
            *(float4 *)&S.sA[it][tid * 4] = v;
        }
        __syncthreads();

        // ---- Phase B compute: h1_new = tanh(h0_new@Wih1 + h1_old@Whh1 + bias) ----
        {
            unsigned long long acc0 = pack2(S.cbias1[cp * 2], S.cbias1[cp * 2 + 1]);
            unsigned long long acc1 = pack2(0.f, 0.f);
            gemm_rc(&S.sA[r][0], &S.wih1T[cp][0], DM, acc0, acc1);
            if (t > 0) gemm_rc(&S.sB[r][0], &S.whh1T[cp][0], DM, acc0, acc1);
            float a, b, c, d;
            unpack2(acc0, a, b);
            unpack2(acc1, c, d);
            float v0 = tanhf(a + c), v1 = tanhf(b + d);
            *(float2 *)&g_h1[nb][(r0 + r) * DM + c0 + cp * 2] = make_float2(v0, v1);
        }

        grid_barrier(++epoch);  // h1_new globally complete
    }

    // ---- Epilogue: out_{T-1} from h1 buffer (T-1)&1 == 1 ----
#pragma unroll 4
    for (int it = 0; it < RB; it++) {
        float4 v = *(const float4 *)&g_h1[1][(r0 + it) * DM + tid * 4];
        *(float4 *)&S.sB[it][tid * 4] = v;
    }
    __syncthreads();
    out_step(S, out, r0, oc0, r, cp, tid, TT - 1);
}

extern "C" void kernel_launch(void *const *d_in, const int *in_sizes, int n_in,
                              void *d_out, int out_size) {
    const float *data = (const float *)d_in[0];
    const float *Wih0 = (const float *)d_in[1];
    const float *bih0 = (const float *)d_in[2];
    const float *Whh0 = (const float *)d_in[3];
    const float *bhh0 = (const float *)d_in[4];
    const float *Wih1 = (const float *)d_in[5];
    const float *bih1 = (const float *)d_in[6];
    const float *Whh1 = (const float *)d_in[7];
    const float *bhh1 = (const float *)d_in[8];
    const float *Wout = (const float *)d_in[9];
    const float *bout = (const float *)d_in[10];
    float *out = (float *)d_out;

    // Persistent kernel needs > 48KB dynamic smem. Attribute is process-wide;
    // calling it every launch is cheap and capture-safe (not a stream op).
    cudaFuncSetAttribute(rnn_persistent_kernel,
                         cudaFuncAttributeMaxDynamicSharedMemorySize,
                         (int)sizeof(Smem));

    rnn_persistent_kernel<<<NCTA, NTHR, sizeof(Smem)>>>(
        data, Wih0, bih0, Whh0, bhh0, Wih1, bih1, Whh1, bhh1, Wout, bout, out);
}

// round 6
// speedup vs baseline: 2.0725x; 2.0725x over previous
#include <cuda_runtime.h>
#include <math.h>

// Problem dims
#define BB   64
#define TT   512
#define DIN  64
#define DM   512
#define DOUT 64

// 128 CTAs = 4 row-blocks x 32 col-blocks, 256 threads each.
#define NCTA 128
#define NTHR 256
#define RB   16     // batch rows per CTA
#define CB   16     // h columns per CTA
#define AST  20     // activation smem stride (floats per k-row), %4==0 for LDS.128
#define WST  16     // weight smem stride

// Ping-pong hidden state in global (L2-resident).
__device__ float g_h0[2][BB * DM];
__device__ float g_h1[2][BB * DM];
// Epoch-parity barrier flags, scoped per row-block group (32 CTAs each).
// Stateless across graph replays: matched by == epoch and every slot is
// rewritten every other epoch within a launch.
__device__ volatile unsigned g_flags[2][4][32];

struct __align__(16) Smem {
    float  sAT[DM][AST];     // h0-side activation, TRANSPOSED [k][row]
    float  sBT[DM][AST];     // h1_old-side activation, transposed
    float  sXT[DIN][AST];    // x_t tile, transposed
    float  whh0T[DM][WST];   // weight slices [k][col]
    float  wih1T[DM][WST];
    float  whh1T[DM][WST];
    float  wih0T[DIN][WST];
    float2 woutT[DM];        // this CTA's 2 output columns of Wout
    float  red[16][RB * CB]; // k-split reduction [ks][r*16+c]
    float2 redo[16][RB];     // out-GEMM reduction [ks][r]
    float  cb0[CB], cb1[CB];
    float2 cbo;
};

// ---- packed f32x2 helpers (Blackwell FFMA2) ----
__device__ __forceinline__ unsigned long long pack2(float lo, float hi) {
    unsigned long long r;
    asm("mov.b64 %0, {%1, %2};" : "=l"(r) : "f"(lo), "f"(hi));
    return r;
}
__device__ __forceinline__ void unpack2(unsigned long long v, float &lo, float &hi) {
    asm("mov.b64 {%0, %1}, %2;" : "=f"(lo), "=f"(hi) : "l"(v));
}
__device__ __forceinline__ void fma2(unsigned long long &d, unsigned long long a,
                                     unsigned long long b) {
    asm("fma.rn.f32x2 %0, %1, %2, %0;" : "+l"(d) : "l"(a), "l"(b));
}

// 4 rows x 4 cols register-tile GEMM slice, interleaved 16-way k-split:
// this thread handles k = i*16 + ks.  8 independent accumulators -> full ILP.
__device__ __forceinline__ void mm44(const float (*__restrict__ aT)[AST],
                                     const float (*__restrict__ wT)[WST],
                                     int niter, int ks, int tr4, int tc4,
                                     unsigned long long acc[4][2]) {
#pragma unroll 4
    for (int i = 0; i < niter; i++) {
        int k = i * 16 + ks;
        float4 a = *(const float4 *)&aT[k][tr4];
        float4 w = *(const float4 *)&wT[k][tc4];
        unsigned long long w01 = pack2(w.x, w.y);
        unsigned long long w23 = pack2(w.z, w.w);
        fma2(acc[0][0], pack2(a.x, a.x), w01);
        fma2(acc[0][1], pack2(a.x, a.x), w23);
        fma2(acc[1][0], pack2(a.y, a.y), w01);
        fma2(acc[1][1], pack2(a.y, a.y), w23);
        fma2(acc[2][0], pack2(a.z, a.z), w01);
        fma2(acc[2][1], pack2(a.z, a.z), w23);
        fma2(acc[3][0], pack2(a.w, a.w), w01);
        fma2(acc[3][1], pack2(a.w, a.w), w23);
    }
}

// Scatter partials, k-split reduce, add bias, tanh, store to global h.
__device__ __forceinline__ void reduce_tanh_store(Smem &S, unsigned long long acc[4][2],
                                                  int ks, int tr4, int tc4,
                                                  const float *__restrict__ cbias,
                                                  float *__restrict__ gdst, int r0,
                                                  int c0, int tid) {
#pragma unroll
    for (int rr = 0; rr < 4; rr++) {
#pragma unroll
        for (int cp = 0; cp < 2; cp++) {
            float x, y;
            unpack2(acc[rr][cp], x, y);
            *(float2 *)&S.red[ks][(tr4 + rr) * CB + tc4 + cp * 2] = make_float2(x, y);
        }
    }
    __syncthreads();
    int r = tid >> 4, c = tid & 15;
    float s = cbias[c];
#pragma unroll
    for (int j = 0; j < 16; j++) s += S.red[j][r * CB + c];
    gdst[(r0 + r) * DM + c0 + c] = tanhf(s);
}

// out_{tt} = sBT-rows @ Wout_slice + bout  (16-way k-split + reduce)
__device__ __forceinline__ void out_step(Smem &S, float *__restrict__ out, int r0,
                                         int oc0, int ks, int tid, int tt) {
    int r = tid & 15;
    unsigned long long o = pack2(0.f, 0.f);
#pragma unroll 4
    for (int i = 0; i < 32; i++) {
        int k = i * 16 + ks;
        float a = S.sBT[k][r];
        float2 w = S.woutT[k];
        fma2(o, pack2(a, a), pack2(w.x, w.y));
    }
    float x, y;
    unpack2(o, x, y);
    S.redo[ks][r] = make_float2(x, y);
    __syncthreads();
    if (tid < RB) {
        float s0 = S.cbo.x, s1 = S.cbo.y;
#pragma unroll
        for (int j = 0; j < 16; j++) {
            float2 p = S.redo[j][tid];
            s0 += p.x;
            s1 += p.y;
        }
        *(float2 *)&out[((size_t)(r0 + tid) * TT + tt) * DOUT + oc0] =
            make_float2(s0, s1);
    }
}

// Transposed staging: global h rows r0..r0+15 -> sT[k][row].
// Per iter: 4 coalesced LDG.32 (lanes span consecutive k) + 1 STS.128.
__device__ __forceinline__ void stage_T(float (*__restrict__ dst)[AST],
                                        const float *__restrict__ src, int r0,
                                        int tid) {
#pragma unroll
    for (int it = 0; it < 8; it++) {
        int idx = it * NTHR + tid;  // 0..2047
        int k = idx & 511, rg = (idx >> 9) * 4;
        float v0 = src[(r0 + rg + 0) * DM + k];
        float v1 = src[(r0 + rg + 1) * DM + k];
        float v2 = src[(r0 + rg + 2) * DM + k];
        float v3 = src[(r0 + rg + 3) * DM + k];
        *(float4 *)&dst[k][rg] = make_float4(v0, v1, v2, v3);
    }
}

// Row-group barrier over the 32 CTAs sharing this rb. __threadfence (gpu scope)
// emits CCTL.IVALL on sm_103a: release of h stores before the flag, and L1
// invalidate after, so staged h reads are coherent.
__device__ __forceinline__ void group_barrier(unsigned e, int rb, int cb, int tid) {
    __threadfence();
    __syncthreads();
    if (tid == 0) g_flags[e & 1u][rb][cb] = e;
    bool ok;
    do {
        ok = (tid < 32) ? (g_flags[e & 1u][rb][tid] == e) : true;
    } while (!__syncthreads_and(ok));
    __threadfence();
}

__global__ void __launch_bounds__(NTHR, 1)
rnn_persistent_kernel(const float *__restrict__ data, const float *__restrict__ Wih0,
                      const float *__restrict__ bih0, const float *__restrict__ Whh0,
                      const float *__restrict__ bhh0, const float *__restrict__ Wih1,
                      const float *__restrict__ bih1, const float *__restrict__ Whh1,
                      const float *__restrict__ bhh1, const float *__restrict__ Wout,
                      const float *__restrict__ bout, float *__restrict__ out) {
    extern __shared__ char smem_raw[];
    Smem &S = *reinterpret_cast<Smem *>(smem_raw);

    const int tid = threadIdx.x;
    const int cta = blockIdx.x;
    const int rb = cta >> 5;   // 0..3
    const int cb = cta & 31;   // 0..31
    const int r0 = rb * RB;
    const int c0 = cb * CB;
    const int oc0 = cb * 2;
    // GEMM thread mapping: 16-way k-split x (4x4 tile positions)
    const int ks = tid >> 4;             // 0..15
    const int tr4 = ((tid >> 2) & 3) * 4;  // tile row base
    const int tc4 = (tid & 3) * 4;         // tile col base

    // ---- one-time: weights -> smem ----
    for (int idx = tid; idx < DM * 16; idx += NTHR) {
        int k = idx >> 4, c = idx & 15;
        S.whh0T[k][c] = Whh0[k * DM + c0 + c];
        S.wih1T[k][c] = Wih1[k * DM + c0 + c];
        S.whh1T[k][c] = Whh1[k * DM + c0 + c];
    }
    for (int idx = tid; idx < DIN * 16; idx += NTHR) {
        int k = idx >> 4, c = idx & 15;
        S.wih0T[k][c] = Wih0[k * DM + c0 + c];
    }
    for (int k = tid; k < DM; k += NTHR)
        S.woutT[k] = *(const float2 *)&Wout[k * DOUT + oc0];
    if (tid < CB) {
        S.cb0[tid] = bih0[c0 + tid] + bhh0[c0 + tid];
        S.cb1[tid] = bih1[c0 + tid] + bhh1[c0 + tid];
    }
    if (tid == 0) S.cbo = make_float2(bout[oc0], bout[oc0 + 1]);
    __syncthreads();

    unsigned epoch = 0;

#pragma unroll 1
    for (int t = 0; t < TT; t++) {
        const int nb = t & 1;
        const int ob = nb ^ 1;

        // ---- Phase A staging: sXT = x_t (transposed); sBT = h1_old (t>0).
        // sAT already holds h0_old (staged during previous phase B).
        {
            int k = tid & 63, rg = (tid >> 6) * 4;
            float v0 = data[((size_t)(r0 + rg + 0) * TT + t) * DIN + k];
            float v1 = data[((size_t)(r0 + rg + 1) * TT + t) * DIN + k];
            float v2 = data[((size_t)(r0 + rg + 2) * TT + t) * DIN + k];
            float v3 = data[((size_t)(r0 + rg + 3) * TT + t) * DIN + k];
            *(float4 *)&S.sXT[k][rg] = make_float4(v0, v1, v2, v3);
        }
        if (t > 0) stage_T(S.sBT, g_h1[ob], r0, tid);
        __syncthreads();

        // ---- Phase A: h0_new = tanh(x@Wih0 + h0_old@Whh0 + bias) ----
        {
            unsigned long long acc[4][2];
#pragma unroll
            for (int i = 0; i < 4; i++) acc[i][0] = acc[i][1] = pack2(0.f, 0.f);
            mm44(S.sXT, S.wih0T, 4, ks, tr4, tc4, acc);
            if (t > 0) mm44(S.sAT, S.whh0T, 32, ks, tr4, tc4, acc);
            reduce_tanh_store(S, acc, ks, tr4, tc4, S.cb0, g_h0[nb], r0, c0, tid);
        }
        // out_{t-1} = h1_old @ Wout + bout (h1_old rows are in sBT)
        if (t > 0) {
            __syncthreads();  // red done before redo phase reuses barriers
            out_step(S, out, r0, oc0, ks, tid, t - 1);
        }

        group_barrier(++epoch, rb, cb, tid);  // h0_new complete in row group

        // ---- Phase B staging: sAT = h0_new (also h0_old for next step) ----
        stage_T(S.sAT, g_h0[nb], r0, tid);
        __syncthreads();

        // ---- Phase B: h1_new = tanh(h0_new@Wih1 + h1_old@Whh1 + bias) ----
        {
            unsigned long long acc[4][2];
#pragma unroll
            for (int i = 0; i < 4; i++) acc[i][0] = acc[i][1] = pack2(0.f, 0.f);
            mm44(S.sAT, S.wih1T, 32, ks, tr4, tc4, acc);
            if (t > 0) mm44(S.sBT, S.whh1T, 32, ks, tr4, tc4, acc);
            reduce_tanh_store(S, acc, ks, tr4, tc4, S.cb1, g_h1[nb], r0, c0, tid);
        }

        group_barrier(++epoch, rb, cb, tid);  // h1_new complete in row group
    }

    // ---- Epilogue: out_{T-1} from g_h1[(T-1)&1 == 1] ----
    stage_T(S.sBT, g_h1[1], r0, tid);
    __syncthreads();
    out_step(S, out, r0, oc0, ks, tid, TT - 1);
}

extern "C" void kernel_launch(void *const *d_in, const int *in_sizes, int n_in,
                              void *d_out, int out_size) {
    const float *data = (const float *)d_in[0];
    const float *Wih0 = (const float *)d_in[1];
    const float *bih0 = (const float *)d_in[2];
    const float *Whh0 = (const float *)d_in[3];
    const float *bhh0 = (const float *)d_in[4];
    const float *Wih1 = (const float *)d_in[5];
    const float *bih1 = (const float *)d_in[6];
    const float *Whh1 = (const float *)d_in[7];
    const float *bhh1 = (const float *)d_in[8];
    const float *Wout = (const float *)d_in[9];
    const float *bout = (const float *)d_in[10];
    float *out = (float *)d_out;

    cudaFuncSetAttribute(rnn_persistent_kernel,
                         cudaFuncAttributeMaxDynamicSharedMemorySize,
                         (int)sizeof(Smem));

    rnn_persistent_kernel<<<NCTA, NTHR, sizeof(Smem)>>>(
        data, Wih0, bih0, Whh0, bhh0, Wih1, bih1, Whh1, bhh1, Wout, bout, out);
}

// round 7
// speedup vs baseline: 2.4903x; 1.2016x over previous
#include <cuda_runtime.h>
#include <math.h>

// Problem dims
#define BB   64
#define TT   512
#define DIN  64
#define DM   512
#define DOUT 64

// 128 CTAs = 4 row-blocks x 32 col-blocks, 512 threads each.
#define NCTA 128
#define NTHR 512
#define RB   16   // batch rows per CTA
#define CB   16   // h columns per CTA
#define AST  20   // h-activation smem row stride (floats)
#define XST  18   // x-activation smem row stride
#define WST  16   // weight smem row stride
#define RS   18   // reduction array output-row stride (pad vs 16)

// Ping-pong hidden state in global (L2-resident).
__device__ float g_h0[2][BB * DM];
__device__ float g_h1[2][BB * DM];
// Epoch-parity barrier flags, scoped per row-block group (32 CTAs).
// Safe across graph replays: slots end each run holding the final epoch,
// which can never equal epoch 1 of the next run before being rewritten.
__device__ volatile unsigned g_flags[2][4][32];

struct __align__(16) Smem {
    float  sAT[DM][AST];      // h0(t), transposed [k][row]
    float  sBT[DM][AST];      // h1(t-1), transposed
    float  sXT[DIN][XST];     // x(t+1) tile, transposed
    float  whh0T[DM][WST];    // weight col-slices [k][col]
    float  wih1T[DM][WST];
    float  whh1T[DM][WST];
    float  wih0T[DIN][WST];
    float2 woutT[DM];         // 2 output columns of Wout
    float  redB[16][CB * RS]; // layer-1 k-split partials
    float  redA[16][CB * RS]; // layer-0 k-split partials
    float  redo[16][33];      // out-GEMM partials
    float  cb0[CB], cb1[CB];
    float2 cbo;
};

// ---- packed f32x2 helpers (Blackwell FFMA2) ----
__device__ __forceinline__ unsigned long long pack2(float lo, float hi) {
    unsigned long long r;
    asm("mov.b64 %0, {%1, %2};" : "=l"(r) : "f"(lo), "f"(hi));
    return r;
}
__device__ __forceinline__ void unpack2(unsigned long long v, float &lo, float &hi) {
    asm("mov.b64 {%0, %1}, %2;" : "=f"(lo), "=f"(hi) : "l"(v));
}
__device__ __forceinline__ void fma2(unsigned long long &d, unsigned long long a,
                                     unsigned long long b) {
    asm("fma.rn.f32x2 %0, %1, %2, %0;" : "+l"(d) : "l"(a), "l"(b));
}

// 2 rows x 4 cols per-thread tile, 16-way k-split with ks = warp id, so every
// smem access in the loop has warp-uniform k: w LDS.128 = 4-address broadcast,
// a LDS.64 hits 16 distinct banks. 4 FFMA2 + 1 LDS.64 + 1 LDS.128 + 2 packs.
template <int N16, int ASTR>
__device__ __forceinline__ void mmT(const float *__restrict__ aT,
                                    const float *__restrict__ wT, int ks, int r2,
                                    int c4, unsigned long long acc[2][2]) {
#pragma unroll
    for (int i = 0; i < N16; i++) {
        int k = i * 16 + ks;
        float2 a = *(const float2 *)&aT[k * ASTR + r2];
        float4 w = *(const float4 *)&wT[k * WST + c4];
        unsigned long long a0 = pack2(a.x, a.x);
        unsigned long long a1 = pack2(a.y, a.y);
        unsigned long long w01 = pack2(w.x, w.y);
        unsigned long long w23 = pack2(w.z, w.w);
        fma2(acc[0][0], a0, w01);
        fma2(acc[0][1], a0, w23);
        fma2(acc[1][0], a1, w01);
        fma2(acc[1][1], a1, w23);
    }
}

__device__ __forceinline__ void scatter(float (*__restrict__ red)[CB * RS],
                                        unsigned long long acc[2][2], int ks, int r2,
                                        int c4) {
#pragma unroll
    for (int r = 0; r < 2; r++)
#pragma unroll
        for (int cp = 0; cp < 2; cp++) {
            float x, y;
            unpack2(acc[r][cp], x, y);
            *(float2 *)&red[ks][(r2 + r) * RS + c4 + 2 * cp] = make_float2(x, y);
        }
}

__device__ __forceinline__ void finalReduceH(const float (*__restrict__ red)[CB * RS],
                                             const float *__restrict__ cb,
                                             float *__restrict__ gdst, int o, int r0,
                                             int c0) {
    int orr = o >> 4, oc = o & 15;
    float s = cb[oc];
#pragma unroll
    for (int j = 0; j < 16; j++) s += red[j][orr * RS + oc];
    gdst[(r0 + orr) * DM + c0 + oc] = tanhf(s);
}

// Staging: global h rows r0..r0+15 -> dst[k][row]. Each warp covers 8 k x 4
// row-groups whose STS.128s tile all 32 banks exactly (4 phases, optimal).
__device__ __forceinline__ void stageH(float (*__restrict__ dst)[AST],
                                       const float *__restrict__ src, int r0,
                                       int tid) {
#pragma unroll
    for (int it = 0; it < 4; it++) {
        int task = it * NTHR + tid;
        int q = task >> 5, g = (task >> 3) & 3, l = task & 7;
        int k = q * 8 + l, rg = g * 4;
        float4 v;
        v.x = src[(r0 + rg + 0) * DM + k];
        v.y = src[(r0 + rg + 1) * DM + k];
        v.z = src[(r0 + rg + 2) * DM + k];
        v.w = src[(r0 + rg + 3) * DM + k];
        *(float4 *)&dst[k][rg] = v;
    }
}

__device__ __forceinline__ void stageX(Smem &S, const float *__restrict__ data,
                                       int r0, int tx, int tid) {
    int k = tid >> 3, rr = (tid & 7) * 2;
    float2 v;
    v.x = data[((r0 + rr) * TT + tx) * DIN + k];
    v.y = data[((r0 + rr + 1) * TT + tx) * DIN + k];
    *(float2 *)&S.sXT[k][rr] = v;
}

// Row-group barrier (32 CTAs). Pre-fence orders h stores before flag; warp 0
// polls all 32 flags; post-fence (CCTL.IVALL, SM-wide L1 invalidate) makes
// peer h stores visible to subsequent staging loads.
__device__ __forceinline__ void group_barrier(unsigned e, int rb, int cb, int tid) {
    __threadfence();
    __syncthreads();
    if (tid == 0) g_flags[e & 1u][rb][cb] = e;
    if (tid < 32) {
        while (!__all_sync(0xffffffffu, g_flags[e & 1u][rb][tid] == e)) {
        }
        __threadfence();
    }
    __syncthreads();
}

__global__ void __launch_bounds__(NTHR, 1)
rnn_persistent_kernel(const float *__restrict__ data, const float *__restrict__ Wih0,
                      const float *__restrict__ bih0, const float *__restrict__ Whh0,
                      const float *__restrict__ bhh0, const float *__restrict__ Wih1,
                      const float *__restrict__ bih1, const float *__restrict__ Whh1,
                      const float *__restrict__ bhh1, const float *__restrict__ Wout,
                      const float *__restrict__ bout, float *__restrict__ out) {
    extern __shared__ char smem_raw[];
    Smem &S = *reinterpret_cast<Smem *>(smem_raw);

    const int tid = threadIdx.x;
    const int cta = blockIdx.x;
    const int rb = cta >> 5;   // 0..3
    const int cb = cta & 31;   // 0..31
    const int r0 = rb * RB;
    const int c0 = cb * CB;
    const int oc0 = cb * 2;
    // GEMM mapping: ks = warp id (16-way k-split), 32 tile positions
    const int ks = tid >> 5;
    const int pos = tid & 31;
    const int r2 = (pos >> 2) * 2;  // rows r2, r2+1
    const int c4 = (pos & 3) * 4;   // cols c4..c4+3
    // out-GEMM mapping
    const int orow = pos >> 1, ocol = pos & 1;

    // ---- one-time: weights -> smem ----
    for (int idx = tid; idx < DM * 16; idx += NTHR) {
        int k = idx >> 4, c = idx & 15;
        S.whh0T[k][c] = Whh0[k * DM + c0 + c];
        S.wih1T[k][c] = Wih1[k * DM + c0 + c];
        S.whh1T[k][c] = Whh1[k * DM + c0 + c];
    }
    for (int idx = tid; idx < DIN * 16; idx += NTHR) {
        int k = idx >> 4, c = idx & 15;
        S.wih0T[k][c] = Wih0[k * DM + c0 + c];
    }
    for (int k = tid; k < DM; k += NTHR)
        S.woutT[k] = *(const float2 *)&Wout[k * DOUT + oc0];
    if (tid < CB) {
        S.cb0[tid] = bih0[c0 + tid] + bhh0[c0 + tid];
        S.cb1[tid] = bih1[c0 + tid] + bhh1[c0 + tid];
    }
    if (tid == 0) S.cbo = make_float2(bout[oc0], bout[oc0 + 1]);

    // ---- prologue: h0(0) = tanh(x(0) @ Wih0 + b0) ----
    stageX(S, data, r0, 0, tid);
    __syncthreads();
    {
        unsigned long long acc[2][2];
        acc[0][0] = acc[0][1] = acc[1][0] = acc[1][1] = pack2(0.f, 0.f);
        mmT<4, XST>(&S.sXT[0][0], &S.wih0T[0][0], ks, r2, c4, acc);
        scatter(S.redA, acc, ks, r2, c4);
    }
    __syncthreads();
    if (tid >= 256) finalReduceH(S.redA, S.cb0, g_h0[0], tid - 256, r0, c0);

    unsigned epoch = 1;
    group_barrier(epoch, rb, cb, tid);

#pragma unroll 1
    for (int t = 0; t < TT; t++) {
        // Buffers: h0(t) in g_h0[t&1]; h1(t-1) in g_h1[(t+1)&1].
        // This iteration writes h1(t) -> g_h1[t&1], h0(t+1) -> g_h0[(t+1)&1].
        stageH(S.sAT, g_h0[t & 1], r0, tid);
        if (t > 0) stageH(S.sBT, g_h1[(t + 1) & 1], r0, tid);
        if (t < TT - 1) stageX(S, data, r0, t + 1, tid);
        __syncthreads();

        // layer-1 partials: h1(t) = tanh(h0(t)@Wih1 + h1(t-1)@Whh1 + b1)
        {
            unsigned long long acc[2][2];
            acc[0][0] = acc[0][1] = acc[1][0] = acc[1][1] = pack2(0.f, 0.f);
            mmT<32, AST>(&S.sAT[0][0], &S.wih1T[0][0], ks, r2, c4, acc);
            if (t > 0) mmT<32, AST>(&S.sBT[0][0], &S.whh1T[0][0], ks, r2, c4, acc);
            scatter(S.redB, acc, ks, r2, c4);
        }
        // layer-0 partials for NEXT step: h0(t+1) = tanh(x(t+1)@Wih0 + h0(t)@Whh0 + b0)
        if (t < TT - 1) {
            unsigned long long acc[2][2];
            acc[0][0] = acc[0][1] = acc[1][0] = acc[1][1] = pack2(0.f, 0.f);
            mmT<4, XST>(&S.sXT[0][0], &S.wih0T[0][0], ks, r2, c4, acc);
            mmT<32, AST>(&S.sAT[0][0], &S.whh0T[0][0], ks, r2, c4, acc);
            scatter(S.redA, acc, ks, r2, c4);
        }
        // out(t-1) partials from h1(t-1) (in sBT)
        if (t > 0) {
            float oa = 0.f;
#pragma unroll 8
            for (int i = 0; i < 32; i++) {
                int k = i * 16 + ks;
                float a = S.sBT[k][orow];
                float2 wv = S.woutT[k];
                oa += a * (ocol ? wv.y : wv.x);
            }
            S.redo[ks][pos] = oa;
        }
        __syncthreads();

        // split final reduces: half threads layer-1, half layer-0
        if (tid < 256) {
            finalReduceH(S.redB, S.cb1, g_h1[t & 1], tid, r0, c0);
            if (t > 0 && tid < 32) {
                float s = (tid & 1) ? S.cbo.y : S.cbo.x;
#pragma unroll
                for (int j = 0; j < 16; j++) s += S.redo[j][tid];
                out[((r0 + (tid >> 1)) * TT + (t - 1)) * DOUT + oc0 + (tid & 1)] = s;
            }
        } else if (t < TT - 1) {
            finalReduceH(S.redA, S.cb0, g_h0[(t + 1) & 1], tid - 256, r0, c0);
        }

        group_barrier(++epoch, rb, cb, tid);
    }

    // ---- epilogue: out(T-1) from h1(T-1) in g_h1[1] ----
    stageH(S.sBT, g_h1[1], r0, tid);
    __syncthreads();
    {
        float oa = 0.f;
#pragma unroll 8
        for (int i = 0; i < 32; i++) {
            int k = i * 16 + ks;
            float a = S.sBT[k][orow];
            float2 wv = S.woutT[k];
            oa += a * (ocol ? wv.y : wv.x);
        }
        S.redo[ks][pos] = oa;
    }
    __syncthreads();
    if (tid < 32) {
        float s = (tid & 1) ? S.cbo.y : S.cbo.x;
#pragma unroll
        for (int j = 0; j < 16; j++) s += S.redo[j][tid];
        out[((r0 + (tid >> 1)) * TT + (TT - 1)) * DOUT + oc0 + (tid & 1)] = s;
    }
}

extern "C" void kernel_launch(void *const *d_in, const int *in_sizes, int n_in,
                              void *d_out, int out_size) {
    const float *data = (const float *)d_in[0];
    const float *Wih0 = (const float *)d_in[1];
    const float *bih0 = (const float *)d_in[2];
    const float *Whh0 = (const float *)d_in[3];
    const float *bhh0 = (const float *)d_in[4];
    const float *Wih1 = (const float *)d_in[5];
    const float *bih1 = (const float *)d_in[6];
    const float *Whh1 = (const float *)d_in[7];
    const float *bhh1 = (const float *)d_in[8];
    const float *Wout = (const float *)d_in[9];
    const float *bout = (const float *)d_in[10];
    float *out = (float *)d_out;

    cudaFuncSetAttribute(rnn_persistent_kernel,
                         cudaFuncAttributeMaxDynamicSharedMemorySize,
                         (int)sizeof(Smem));

    rnn_persistent_kernel<<<NCTA, NTHR, sizeof(Smem)>>>(
        data, Wih0, bih0, Whh0, bhh0, Wih1, bih1, Whh1, bhh1, Wout, bout, out);
}

// round 8
// speedup vs baseline: 2.7851x; 1.1184x over previous
#include <cuda_runtime.h>
#include <math.h>

// Problem dims
#define BB   64
#define TT   512
#define DIN  64
#define DM   512
#define DOUT 64

// 128 CTAs = 4 row-blocks x 32 col-blocks, 512 threads each.
#define NCTA 128
#define NTHR 512
#define RB   16   // batch rows per CTA
#define CB   16   // h columns per CTA
#define AST  20   // h-activation smem row stride (floats)
#define XST  18   // x-activation smem row stride
#define WST  16   // weight smem row stride
#define RS   18   // reduction array output-row stride (pad vs 16)

// Ping-pong hidden state in global (L2-resident, accessed .cg only).
__device__ float g_h0[2][BB * DM];
__device__ float g_h1[2][BB * DM];
// Epoch-parity barrier flags, scoped per row-block group (32 CTAs).
// Stateless across graph replays: stale values from a previous run are all
// larger than the epochs that first probe each parity slot (1 and 2).
__device__ unsigned g_flags[2][4][32];

struct __align__(16) Smem {
    float  sAT[DM][AST];      // h0(t), transposed [k][row]
    float  sBT[DM][AST];      // h1(t-1), transposed
    float  sXT[DIN][XST];     // x(t+1) tile, transposed
    float  whh0T[DM][WST];    // weight col-slices [k][col]
    float  wih1T[DM][WST];
    float  whh1T[DM][WST];
    float  wih0T[DIN][WST];
    float2 woutT[DM];         // 2 output columns of Wout
    float  redB[16][CB * RS]; // layer-1 k-split partials
    float  redA[16][CB * RS]; // layer-0 k-split partials
    float  redo[16][33];      // out-GEMM partials
    float  cb0[CB], cb1[CB];
    float2 cbo;
};

// ---- L2-direct (L1-bypass) accessors for the exchanged hidden state ----
__device__ __forceinline__ float ldcg(const float *p) {
    float v;
    asm volatile("ld.global.cg.f32 %0, [%1];" : "=f"(v) : "l"(p));
    return v;
}
__device__ __forceinline__ void stcg(float *p, float v) {
    asm volatile("st.global.cg.f32 [%0], %1;" ::"l"(p), "f"(v));
}

// ---- barrier primitives: CG-style release/acquire, no CCTL.IVALL ----
__device__ __forceinline__ void flag_arrive(unsigned e, int rb, int cb) {
    asm volatile("st.release.gpu.u32 [%0], %1;" ::"l"(&g_flags[e & 1u][rb][cb]),
                 "r"(e)
                 : "memory");
}
__device__ __forceinline__ void flag_wait(unsigned e, int rb, int lane) {
    unsigned v;
    do {  // 32 consecutive u32 flags -> one coalesced 128B L2 probe per round
        asm volatile("ld.acquire.gpu.u32 %0, [%1];"
                     : "=r"(v)
                     : "l"(&g_flags[e & 1u][rb][lane])
                     : "memory");
    } while (!__all_sync(0xffffffffu, v == e));
}

// ---- packed f32x2 helpers (Blackwell FFMA2) ----
__device__ __forceinline__ unsigned long long pack2(float lo, float hi) {
    unsigned long long r;
    asm("mov.b64 %0, {%1, %2};" : "=l"(r) : "f"(lo), "f"(hi));
    return r;
}
__device__ __forceinline__ void unpack2(unsigned long long v, float &lo, float &hi) {
    asm("mov.b64 {%0, %1}, %2;" : "=f"(lo), "=f"(hi) : "l"(v));
}
__device__ __forceinline__ void fma2(unsigned long long &d, unsigned long long a,
                                     unsigned long long b) {
    asm("fma.rn.f32x2 %0, %1, %2, %0;" : "+l"(d) : "l"(a), "l"(b));
}

// 2 rows x 4 cols per-thread tile, 16-way k-split with ks = warp id: every
// smem access has warp-uniform k (w LDS.128 = 4-address broadcast, a LDS.64
// hits 16 distinct banks). 4 FFMA2 per 16 MACs.
template <int N16, int ASTR>
__device__ __forceinline__ void mmT(const float *__restrict__ aT,
                                    const float *__restrict__ wT, int ks, int r2,
                                    int c4, unsigned long long acc[2][2]) {
#pragma unroll
    for (int i = 0; i < N16; i++) {
        int k = i * 16 + ks;
        float2 a = *(const float2 *)&aT[k * ASTR + r2];
        float4 w = *(const float4 *)&wT[k * WST + c4];
        unsigned long long a0 = pack2(a.x, a.x);
        unsigned long long a1 = pack2(a.y, a.y);
        unsigned long long w01 = pack2(w.x, w.y);
        unsigned long long w23 = pack2(w.z, w.w);
        fma2(acc[0][0], a0, w01);
        fma2(acc[0][1], a0, w23);
        fma2(acc[1][0], a1, w01);
        fma2(acc[1][1], a1, w23);
    }
}

__device__ __forceinline__ void scatter(float (*__restrict__ red)[CB * RS],
                                        unsigned long long acc[2][2], int ks, int r2,
                                        int c4) {
#pragma unroll
    for (int r = 0; r < 2; r++)
#pragma unroll
        for (int cp = 0; cp < 2; cp++) {
            float x, y;
            unpack2(acc[r][cp], x, y);
            *(float2 *)&red[ks][(r2 + r) * RS + c4 + 2 * cp] = make_float2(x, y);
        }
}

__device__ __forceinline__ void finalReduceH(const float (*__restrict__ red)[CB * RS],
                                             const float *__restrict__ cb,
                                             float *__restrict__ gdst, int o, int r0,
                                             int c0) {
    int orr = o >> 4, oc = o & 15;
    float s = cb[oc];
#pragma unroll
    for (int j = 0; j < 16; j++) s += red[j][orr * RS + oc];
    stcg(&gdst[(r0 + orr) * DM + c0 + oc], tanhf(s));
}

// Staging: global h rows r0..r0+15 -> dst[k][row], via .cg (L2-coherent).
__device__ __forceinline__ void stageH(float (*__restrict__ dst)[AST],
                                       const float *__restrict__ src, int r0,
                                       int tid) {
#pragma unroll
    for (int it = 0; it < 4; it++) {
        int task = it * NTHR + tid;
        int q = task >> 5, g = (task >> 3) & 3, l = task & 7;
        int k = q * 8 + l, rg = g * 4;
        float4 v;
        v.x = ldcg(&src[(r0 + rg + 0) * DM + k]);
        v.y = ldcg(&src[(r0 + rg + 1) * DM + k]);
        v.z = ldcg(&src[(r0 + rg + 2) * DM + k]);
        v.w = ldcg(&src[(r0 + rg + 3) * DM + k]);
        *(float4 *)&dst[k][rg] = v;
    }
}

__device__ __forceinline__ void stageX(Smem &S, const float *__restrict__ data,
                                       int r0, int tx, int tid) {
    int k = tid >> 3, rr = (tid & 7) * 2;
    float2 v;
    v.x = data[((r0 + rr) * TT + tx) * DIN + k];
    v.y = data[((r0 + rr + 1) * TT + tx) * DIN + k];
    *(float2 *)&S.sXT[k][rr] = v;
}

// out-GEMM partial for this thread (2-accumulator dot over its k-split).
__device__ __forceinline__ float out_partial(const Smem &S, int ks, int orow,
                                             int ocol) {
    float oa0 = 0.f, oa1 = 0.f;
#pragma unroll
    for (int i = 0; i < 32; i += 2) {
        int k0 = i * 16 + ks, k1 = (i + 1) * 16 + ks;
        float2 w0 = S.woutT[k0], w1 = S.woutT[k1];
        oa0 += S.sBT[k0][orow] * (ocol ? w0.y : w0.x);
        oa1 += S.sBT[k1][orow] * (ocol ? w1.y : w1.x);
    }
    return oa0 + oa1;
}

__global__ void __launch_bounds__(NTHR, 1)
rnn_persistent_kernel(const float *__restrict__ data, const float *__restrict__ Wih0,
                      const float *__restrict__ bih0, const float *__restrict__ Whh0,
                      const float *__restrict__ bhh0, const float *__restrict__ Wih1,
                      const float *__restrict__ bih1, const float *__restrict__ Whh1,
                      const float *__restrict__ bhh1, const float *__restrict__ Wout,
                      const float *__restrict__ bout, float *__restrict__ out) {
    extern __shared__ char smem_raw[];
    Smem &S = *reinterpret_cast<Smem *>(smem_raw);

    const int tid = threadIdx.x;
    const int cta = blockIdx.x;
    const int rb = cta >> 5;   // 0..3
    const int cb = cta & 31;   // 0..31
    const int r0 = rb * RB;
    const int c0 = cb * CB;
    const int oc0 = cb * 2;
    // GEMM mapping: ks = warp id (16-way k-split), 32 tile positions
    const int ks = tid >> 5;
    const int pos = tid & 31;
    const int r2 = (pos >> 2) * 2;  // rows r2, r2+1
    const int c4 = (pos & 3) * 4;   // cols c4..c4+3
    // out-GEMM mapping
    const int orow = pos >> 1, ocol = pos & 1;

    // ---- one-time: weights -> smem ----
    for (int idx = tid; idx < DM * 16; idx += NTHR) {
        int k = idx >> 4, c = idx & 15;
        S.whh0T[k][c] = Whh0[k * DM + c0 + c];
        S.wih1T[k][c] = Wih1[k * DM + c0 + c];
        S.whh1T[k][c] = Whh1[k * DM + c0 + c];
    }
    for (int idx = tid; idx < DIN * 16; idx += NTHR) {
        int k = idx >> 4, c = idx & 15;
        S.wih0T[k][c] = Wih0[k * DM + c0 + c];
    }
    for (int k = tid; k < DM; k += NTHR)
        S.woutT[k] = *(const float2 *)&Wout[k * DOUT + oc0];
    if (tid < CB) {
        S.cb0[tid] = bih0[c0 + tid] + bhh0[c0 + tid];
        S.cb1[tid] = bih1[c0 + tid] + bhh1[c0 + tid];
    }
    if (tid == 0) S.cbo = make_float2(bout[oc0], bout[oc0 + 1]);

    // ---- prologue: h0(0) = tanh(x(0) @ Wih0 + b0) ----
    stageX(S, data, r0, 0, tid);
    __syncthreads();
    {
        unsigned long long acc[2][2];
        acc[0][0] = acc[0][1] = acc[1][0] = acc[1][1] = pack2(0.f, 0.f);
        mmT<4, XST>(&S.sXT[0][0], &S.wih0T[0][0], ks, r2, c4, acc);
        scatter(S.redA, acc, ks, r2, c4);
    }
    __syncthreads();
    if (tid >= 256) finalReduceH(S.redA, S.cb0, g_h0[0], tid - 256, r0, c0);

    unsigned epoch = 1;
    __syncthreads();
    if (tid == 0) flag_arrive(epoch, rb, cb);
    if (tid < 32) flag_wait(epoch, rb, tid);
    __syncthreads();

#pragma unroll 1
    for (int t = 0; t < TT; t++) {
        // Buffers: h0(t) in g_h0[t&1]; h1(t-1) in g_h1[(t+1)&1].
        // This iteration writes h1(t) -> g_h1[t&1], h0(t+1) -> g_h0[(t+1)&1].
        stageH(S.sAT, g_h0[t & 1], r0, tid);
        if (t > 0) stageH(S.sBT, g_h1[(t + 1) & 1], r0, tid);
        if (t < TT - 1) stageX(S, data, r0, t + 1, tid);
        __syncthreads();

        // layer-1 partials: h1(t) = tanh(h0(t)@Wih1 + h1(t-1)@Whh1 + b1)
        {
            unsigned long long acc[2][2];
            acc[0][0] = acc[0][1] = acc[1][0] = acc[1][1] = pack2(0.f, 0.f);
            mmT<32, AST>(&S.sAT[0][0], &S.wih1T[0][0], ks, r2, c4, acc);
            if (t > 0) mmT<32, AST>(&S.sBT[0][0], &S.whh1T[0][0], ks, r2, c4, acc);
            scatter(S.redB, acc, ks, r2, c4);
        }
        // layer-0 partials for NEXT step: h0(t+1) = tanh(x(t+1)@Wih0 + h0(t)@Whh0 + b0)
        if (t < TT - 1) {
            unsigned long long acc[2][2];
            acc[0][0] = acc[0][1] = acc[1][0] = acc[1][1] = pack2(0.f, 0.f);
            mmT<4, XST>(&S.sXT[0][0], &S.wih0T[0][0], ks, r2, c4, acc);
            mmT<32, AST>(&S.sAT[0][0], &S.whh0T[0][0], ks, r2, c4, acc);
            scatter(S.redA, acc, ks, r2, c4);
        }
        // out(t-1) partials from h1(t-1) (in sBT)
        if (t > 0) S.redo[ks][pos] = out_partial(S, ks, orow, ocol);
        __syncthreads();

        // split final reduces: half threads layer-1, half layer-0
        if (tid < 256) {
            finalReduceH(S.redB, S.cb1, g_h1[t & 1], tid, r0, c0);
        } else if (t < TT - 1) {
            finalReduceH(S.redA, S.cb0, g_h0[(t + 1) & 1], tid - 256, r0, c0);
        }

        // barrier; out(t-1) final reduce hidden between arrive and wait
        epoch++;
        __syncthreads();
        if (tid == 0) flag_arrive(epoch, rb, cb);
        if (tid < 32) {
            if (t > 0) {
                float s = (tid & 1) ? S.cbo.y : S.cbo.x;
#pragma unroll
                for (int j = 0; j < 16; j++) s += S.redo[j][tid];
                out[((r0 + (tid >> 1)) * TT + (t - 1)) * DOUT + oc0 + (tid & 1)] = s;
            }
            flag_wait(epoch, rb, tid);
        }
        __syncthreads();
    }

    // ---- epilogue: out(T-1) from h1(T-1) in g_h1[1] ----
    stageH(S.sBT, g_h1[1], r0, tid);
    __syncthreads();
    S.redo[ks][pos] = out_partial(S, ks, orow, ocol);
    __syncthreads();
    if (tid < 32) {
        float s = (tid & 1) ? S.cbo.y : S.cbo.x;
#pragma unroll
        for (int j = 0; j < 16; j++) s += S.redo[j][tid];
        out[((r0 + (tid >> 1)) * TT + (TT - 1)) * DOUT + oc0 + (tid & 1)] = s;
    }
}

extern "C" void kernel_launch(void *const *d_in, const int *in_sizes, int n_in,
                              void *d_out, int out_size) {
    const float *data = (const float *)d_in[0];
    const float *Wih0 = (const float *)d_in[1];
    const float *bih0 = (const float *)d_in[2];
    const float *Whh0 = (const float *)d_in[3];
    const float *bhh0 = (const float *)d_in[4];
    const float *Wih1 = (const float *)d_in[5];
    const float *bih1 = (const float *)d_in[6];
    const float *Whh1 = (const float *)d_in[7];
    const float *bhh1 = (const float *)d_in[8];
    const float *Wout = (const float *)d_in[9];
    const float *bout = (const float *)d_in[10];
    float *out = (float *)d_out;

    cudaFuncSetAttribute(rnn_persistent_kernel,
                         cudaFuncAttributeMaxDynamicSharedMemorySize,
                         (int)sizeof(Smem));

    rnn_persistent_kernel<<<NCTA, NTHR, sizeof(Smem)>>>(
        data, Wih0, bih0, Whh0, bhh0, Wih1, bih1, Whh1, bhh1, Wout, bout, out);
}

// round 10
// speedup vs baseline: 3.4590x; 1.2419x over previous
#include <cuda_runtime.h>
#include <math.h>

// Problem dims
#define BB   64
#define TT   512
#define DIN  64
#define DM   512
#define DOUT 64

// 128 CTAs = 4 row-blocks x 32 col-blocks, 512 threads each.
#define NCTA 128
#define NTHR 512
#define RB   16   // batch rows per CTA
#define CB   16   // h columns per CTA
#define AST  20   // h-activation smem row stride (floats)
#define XST  18   // x-activation smem row stride (8B-aligned rows only!)
#define WST  16   // weight smem row stride
#define RS   18   // reduction array output-row stride (pad vs 16)

// Transposed ping-pong hidden state in global: [k][batch-row], L2-resident,
// accessed .cg only.
__device__ float g_h0T[2][DM * BB];
__device__ float g_h1T[2][DM * BB];
// Transposed input: g_xT[t][k][row] (written once in a prepass).
__device__ float g_xT[TT * DIN * BB];
// Epoch-parity barrier flags, scoped per row-block group (32 CTAs).
// Stateless across graph replays: stale end-of-run values (514/515) can never
// equal the epochs that first probe each parity slot (1 and 2).
__device__ unsigned g_flags[2][4][32];

struct __align__(16) Smem {
    float  sAT[DM][AST];      // h0(t), transposed [k][row]
    float  sBT[DM][AST];      // h1(t-1), transposed
    float  sXT[DIN][XST];     // x(t+1) tile, transposed
    float  whh0T[DM][WST];    // weight col-slices [k][col]
    float  wih1T[DM][WST];
    float  whh1T[DM][WST];
    float  wih0T[DIN][WST];
    float2 woutT[DM];         // 2 output columns of Wout
    float  redB[16][CB * RS]; // layer-1 k-split partials
    float  redA[16][CB * RS]; // layer-0 k-split partials
    float  redo[16][33];      // out-GEMM partials
    float  cb0[CB], cb1[CB];
    float2 cbo;
};

// ---- L2-direct (L1-bypass) accessors for the exchanged hidden state ----
__device__ __forceinline__ void ldcg4(const float *p, float4 &v) {
    asm volatile("ld.global.cg.v4.f32 {%0,%1,%2,%3}, [%4];"
                 : "=f"(v.x), "=f"(v.y), "=f"(v.z), "=f"(v.w)
                 : "l"(p));
}
__device__ __forceinline__ void stcg(float *p, float v) {
    asm volatile("st.global.cg.f32 [%0], %1;" ::"l"(p), "f"(v));
}

// ---- barrier primitives: CG-style release/acquire, no CCTL.IVALL ----
__device__ __forceinline__ void flag_arrive(unsigned e, int rb, int cb) {
    asm volatile("st.release.gpu.u32 [%0], %1;" ::"l"(&g_flags[e & 1u][rb][cb]),
                 "r"(e)
                 : "memory");
}
__device__ __forceinline__ void flag_wait(unsigned e, int rb, int lane) {
    unsigned v;
    do {  // 32 consecutive u32 flags -> one coalesced 128B L2 probe per round
        asm volatile("ld.acquire.gpu.u32 %0, [%1];"
                     : "=r"(v)
                     : "l"(&g_flags[e & 1u][rb][lane])
                     : "memory");
    } while (!__all_sync(0xffffffffu, v == e));
}

// ---- packed f32x2 helpers (Blackwell FFMA2) ----
__device__ __forceinline__ unsigned long long pack2(float lo, float hi) {
    unsigned long long r;
    asm("mov.b64 %0, {%1, %2};" : "=l"(r) : "f"(lo), "f"(hi));
    return r;
}
__device__ __forceinline__ void unpack2(unsigned long long v, float &lo, float &hi) {
    asm("mov.b64 {%0, %1}, %2;" : "=f"(lo), "=f"(hi) : "l"(v));
}
__device__ __forceinline__ void fma2(unsigned long long &d, unsigned long long a,
                                     unsigned long long b) {
    asm("fma.rn.f32x2 %0, %1, %2, %0;" : "+l"(d) : "l"(a), "l"(b));
}

// Fused 2-row x 4-col tile over one activation stream and up to two weight
// streams. Weight LDS.128 loaded as ulonglong2: its 64-bit halves are direct
// f32x2 operands (zero packing MOVs). Only the activation broadcast needs MOVs.
// 14 issues per 32 MACs when fused.
template <int N16, int ASTR, bool FUSE>
__device__ __forceinline__ void gemm_rc(const float *__restrict__ aT,
                                        const float *__restrict__ w1T,
                                        const float *__restrict__ w2T, int ks,
                                        int r2, int c4,
                                        unsigned long long accB[2][2],
                                        unsigned long long accA[2][2]) {
#pragma unroll 8
    for (int i = 0; i < N16; i++) {
        int k = i * 16 + ks;
        unsigned long long av = *(const unsigned long long *)&aT[k * ASTR + r2];
        ulonglong2 w1 = *(const ulonglong2 *)&w1T[k * WST + c4];
        float ax, ay;
        unpack2(av, ax, ay);
        unsigned long long a0 = pack2(ax, ax);
        unsigned long long a1 = pack2(ay, ay);
        fma2(accB[0][0], a0, w1.x);
        fma2(accB[0][1], a0, w1.y);
        fma2(accB[1][0], a1, w1.x);
        fma2(accB[1][1], a1, w1.y);
        if (FUSE) {
            ulonglong2 w2 = *(const ulonglong2 *)&w2T[k * WST + c4];
            fma2(accA[0][0], a0, w2.x);
            fma2(accA[0][1], a0, w2.y);
            fma2(accA[1][0], a1, w2.x);
            fma2(accA[1][1], a1, w2.y);
        }
    }
}

__device__ __forceinline__ void scatter(float (*__restrict__ red)[CB * RS],
                                        unsigned long long acc[2][2], int ks, int r2,
                                        int c4) {
#pragma unroll
    for (int r = 0; r < 2; r++)
#pragma unroll
        for (int cp = 0; cp < 2; cp++) {
            float x, y;
            unpack2(acc[r][cp], x, y);
            *(float2 *)&red[ks][(r2 + r) * RS + c4 + 2 * cp] = make_float2(x, y);
        }
}

// Final reduce with transposed mapping: orr = o&15, oc = o>>4.
// red reads are conflict-free and stores to transposed global h are coalesced
// (each warp writes 2 contiguous 64B rows of g_hT).
__device__ __forceinline__ void finalReduceH(const float (*__restrict__ red)[CB * RS],
                                             const float *__restrict__ cb,
                                             float *__restrict__ gdstT, int o, int r0,
                                             int c0) {
    int orr = o & 15, oc = o >> 4;
    float s = cb[oc];
#pragma unroll
    for (int j = 0; j < 16; j++) s += red[j][orr * RS + oc];
    stcg(&gdstT[(c0 + oc) * BB + r0 + orr], tanhf(s));
}

// Staging from transposed global h: 4 x (LDG.128.cg + STS.128) per thread.
// dst rows are 80B apart (AST=20) -> 16B-aligned row base, rg multiple of 4.
__device__ __forceinline__ void stageH(float (*__restrict__ dst)[AST],
                                       const float *__restrict__ srcT, int r0,
                                       int tid) {
#pragma unroll
    for (int it = 0; it < 4; it++) {
        int task = it * NTHR + tid;  // 0..2047
        int k = task >> 2, rg = (task & 3) << 2;
        float4 v;
        ldcg4(&srcT[k * BB + r0 + rg], v);
        *(float4 *)&dst[k][rg] = v;
    }
}

// x staging from pre-transposed g_xT (threads 0..255 only).
// NOTE: sXT rows are 72B apart (XST=18) -> only 8B-aligned; must store as
// 2x float2, never float4 (misaligned-address trap otherwise).
__device__ __forceinline__ void stageX(Smem &S, int r0, int tx, int tid) {
    if (tid < 256) {
        int k = tid >> 2, rg = (tid & 3) << 2;
        float4 v = *(const float4 *)&g_xT[((size_t)tx * DIN + k) * BB + r0 + rg];
        *(float2 *)&S.sXT[k][rg] = make_float2(v.x, v.y);
        *(float2 *)&S.sXT[k][rg + 2] = make_float2(v.z, v.w);
    }
}

// out-GEMM partial for this thread (2-accumulator dot over its k-split).
__device__ __forceinline__ float out_partial(const Smem &S, int ks, int orow,
                                             int ocol) {
    float oa0 = 0.f, oa1 = 0.f;
#pragma unroll 8
    for (int i = 0; i < 32; i += 2) {
        int k0 = i * 16 + ks, k1 = (i + 1) * 16 + ks;
        float2 w0 = S.woutT[k0], w1 = S.woutT[k1];
        oa0 += S.sBT[k0][orow] * (ocol ? w0.y : w0.x);
        oa1 += S.sBT[k1][orow] * (ocol ? w1.y : w1.x);
    }
    return oa0 + oa1;
}

__global__ void __launch_bounds__(NTHR, 1)
rnn_persistent_kernel(const float *__restrict__ data, const float *__restrict__ Wih0,
                      const float *__restrict__ bih0, const float *__restrict__ Whh0,
                      const float *__restrict__ bhh0, const float *__restrict__ Wih1,
                      const float *__restrict__ bih1, const float *__restrict__ Whh1,
                      const float *__restrict__ bhh1, const float *__restrict__ Wout,
                      const float *__restrict__ bout, float *__restrict__ out) {
    extern __shared__ char smem_raw[];
    Smem &S = *reinterpret_cast<Smem *>(smem_raw);

    const int tid = threadIdx.x;
    const int cta = blockIdx.x;
    const int rb = cta >> 5;   // 0..3
    const int cb = cta & 31;   // 0..31
    const int r0 = rb * RB;
    const int c0 = cb * CB;
    const int oc0 = cb * 2;
    // GEMM mapping: ks = warp id (16-way k-split), 32 tile positions
    const int ks = tid >> 5;
    const int pos = tid & 31;
    const int r2 = (pos >> 2) * 2;  // rows r2, r2+1
    const int c4 = (pos & 3) * 4;   // cols c4..c4+3
    // out-GEMM mapping
    const int orow = pos >> 1, ocol = pos & 1;

    // ---- one-time: weights -> smem ----
    for (int idx = tid; idx < DM * 16; idx += NTHR) {
        int k = idx >> 4, c = idx & 15;
        S.whh0T[k][c] = Whh0[k * DM + c0 + c];
        S.wih1T[k][c] = Wih1[k * DM + c0 + c];
        S.whh1T[k][c] = Whh1[k * DM + c0 + c];
    }
    for (int idx = tid; idx < DIN * 16; idx += NTHR) {
        int k = idx >> 4, c = idx & 15;
        S.wih0T[k][c] = Wih0[k * DM + c0 + c];
    }
    for (int k = tid; k < DM; k += NTHR)
        S.woutT[k] = *(const float2 *)&Wout[k * DOUT + oc0];
    if (tid < CB) {
        S.cb0[tid] = bih0[c0 + tid] + bhh0[c0 + tid];
        S.cb1[tid] = bih1[c0 + tid] + bhh1[c0 + tid];
    }
    if (tid == 0) S.cbo = make_float2(bout[oc0], bout[oc0 + 1]);

    // ---- prepass: transpose this CTA's share of x into g_xT ----
    // CTA (rb, cb) handles rows r0..r0+15, t in [cb*16, cb*16+16).
#pragma unroll
    for (int it = 0; it < 8; it++) {
        int task = it * NTHR + tid;  // 0..4095
        int tt = cb * 16 + (task >> 8);
        int k = (task >> 2) & 63;
        int rg = (task & 3) << 2;
        float4 v;
        v.x = data[((size_t)(r0 + rg + 0) * TT + tt) * DIN + k];
        v.y = data[((size_t)(r0 + rg + 1) * TT + tt) * DIN + k];
        v.z = data[((size_t)(r0 + rg + 2) * TT + tt) * DIN + k];
        v.w = data[((size_t)(r0 + rg + 3) * TT + tt) * DIN + k];
        *(float4 *)&g_xT[((size_t)tt * DIN + k) * BB + r0 + rg] = v;
    }

    unsigned epoch = 1;  // x(all t) visible within row group
    __syncthreads();
    if (tid == 0) flag_arrive(epoch, rb, cb);
    if (tid < 32) flag_wait(epoch, rb, tid);
    __syncthreads();

    // ---- prologue: h0(0) = tanh(x(0) @ Wih0 + b0) ----
    stageX(S, r0, 0, tid);
    __syncthreads();
    {
        unsigned long long accA[2][2], dummy[2][2];
        accA[0][0] = accA[0][1] = accA[1][0] = accA[1][1] = pack2(0.f, 0.f);
        gemm_rc<4, XST, false>(&S.sXT[0][0], &S.wih0T[0][0], nullptr, ks, r2, c4,
                               accA, dummy);
        scatter(S.redA, accA, ks, r2, c4);
    }
    __syncthreads();
    if (tid >= 256) finalReduceH(S.redA, S.cb0, g_h0T[0], tid - 256, r0, c0);

    epoch++;
    __syncthreads();
    if (tid == 0) flag_arrive(epoch, rb, cb);
    if (tid < 32) flag_wait(epoch, rb, tid);
    __syncthreads();

#pragma unroll 1
    for (int t = 0; t < TT; t++) {
        // Buffers: h0(t) in g_h0T[t&1]; h1(t-1) in g_h1T[(t+1)&1].
        // This iteration writes h1(t) -> g_h1T[t&1], h0(t+1) -> g_h0T[(t+1)&1].
        stageH(S.sAT, g_h0T[t & 1], r0, tid);
        if (t > 0) stageH(S.sBT, g_h1T[(t + 1) & 1], r0, tid);
        stageX(S, r0, (t < TT - 1) ? t + 1 : TT - 1, tid);
        __syncthreads();

        unsigned long long accB[2][2], accA[2][2];
        accB[0][0] = accB[0][1] = accB[1][0] = accB[1][1] = pack2(0.f, 0.f);
        accA[0][0] = accA[0][1] = accA[1][0] = accA[1][1] = pack2(0.f, 0.f);

        // Fused over sAT: accB += sAT@Wih1, accA += sAT@Whh0 (shared a-loads)
        gemm_rc<32, AST, true>(&S.sAT[0][0], &S.wih1T[0][0], &S.whh0T[0][0], ks, r2,
                               c4, accB, accA);
        // accA += x(t+1)@Wih0
        {
            unsigned long long dummy[2][2];
            gemm_rc<4, XST, false>(&S.sXT[0][0], &S.wih0T[0][0], nullptr, ks, r2, c4,
                                   accA, dummy);
        }
        // accB += h1(t-1)@Whh1
        if (t > 0) {
            unsigned long long dummy[2][2];
            gemm_rc<32, AST, false>(&S.sBT[0][0], &S.whh1T[0][0], nullptr, ks, r2,
                                    c4, accB, dummy);
        }
        scatter(S.redB, accB, ks, r2, c4);
        scatter(S.redA, accA, ks, r2, c4);
        // out(t-1) partials from h1(t-1) (in sBT)
        if (t > 0) S.redo[ks][pos] = out_partial(S, ks, orow, ocol);
        __syncthreads();

        // split final reduces: half threads layer-1, half layer-0
        if (tid < 256) {
            finalReduceH(S.redB, S.cb1, g_h1T[t & 1], tid, r0, c0);
        } else {
            finalReduceH(S.redA, S.cb0, g_h0T[(t + 1) & 1], tid - 256, r0, c0);
        }

        // barrier; out(t-1) final reduce hidden between arrive and wait
        epoch++;
        __syncthreads();
        if (tid == 0) flag_arrive(epoch, rb, cb);
        if (tid < 32) {
            if (t > 0) {
                float s = (tid & 1) ? S.cbo.y : S.cbo.x;
#pragma unroll
                for (int j = 0; j < 16; j++) s += S.redo[j][tid];
                out[((r0 + (tid >> 1)) * TT + (t - 1)) * DOUT + oc0 + (tid & 1)] = s;
            }
            flag_wait(epoch, rb, tid);
        }
        __syncthreads();
    }

    // ---- epilogue: out(T-1) from h1(T-1) in g_h1T[1] ----
    stageH(S.sBT, g_h1T[1], r0, tid);
    __syncthreads();
    S.redo[ks][pos] = out_partial(S, ks, orow, ocol);
    __syncthreads();
    if (tid < 32) {
        float s = (tid & 1) ? S.cbo.y : S.cbo.x;
#pragma unroll
        for (int j = 0; j < 16; j++) s += S.redo[j][tid];
        out[((r0 + (tid >> 1)) * TT + (TT - 1)) * DOUT + oc0 + (tid & 1)] = s;
    }
}

extern "C" void kernel_launch(void *const *d_in, const int *in_sizes, int n_in,
                              void *d_out, int out_size) {
    const float *data = (const float *)d_in[0];
    const float *Wih0 = (const float *)d_in[1];
    const float *bih0 = (const float *)d_in[2];
    const float *Whh0 = (const float *)d_in[3];
    const float *bhh0 = (const float *)d_in[4];
    const float *Wih1 = (const float *)d_in[5];
    const float *bih1 = (const float *)d_in[6];
    const float *Whh1 = (const float *)d_in[7];
    const float *bhh1 = (const float *)d_in[8];
    const float *Wout = (const float *)d_in[9];
    const float *bout = (const float *)d_in[10];
    float *out = (float *)d_out;

    cudaFuncSetAttribute(rnn_persistent_kernel,
                         cudaFuncAttributeMaxDynamicSharedMemorySize,
                         (int)sizeof(Smem));

    rnn_persistent_kernel<<<NCTA, NTHR, sizeof(Smem)>>>(
        data, Wih0, bih0, Whh0, bhh0, Wih1, bih1, Whh1, bhh1, Wout, bout, out);
}